// round 2
// baseline (speedup 1.0000x reference)
#include <cuda_runtime.h>

// Shapes (fixed for this problem; sizes re-derived from in_sizes at launch)
static const int NMAX = 20000;

// Scratch (device globals: no allocation allowed)
__device__ __align__(16) float g_msg_src[NMAX * 128];
__device__ __align__(16) float g_msg_tgt[NMAX * 128];
__device__ __align__(16) float g_skip[NMAX * 128];
__device__ __align__(16) float g_acc[NMAX * 128];
__device__ float g_den[NMAX];

__global__ void zero_kernel(int n) {
    float4 z = make_float4(0.f, 0.f, 0.f, 0.f);
    int stride = gridDim.x * blockDim.x;
    int tot4 = n * 32;  // n*128 floats as float4
    for (int i = blockIdx.x * blockDim.x + threadIdx.x; i < tot4; i += stride)
        reinterpret_cast<float4*>(g_acc)[i] = z;
    for (int i = blockIdx.x * blockDim.x + threadIdx.x; i < n; i += stride)
        g_den[i] = 0.f;
}

// out(which) = x @ W (+bias). which: 0=msg_src, 1=msg_tgt, 2=skip
__global__ void __launch_bounds__(256, 1) node_gemm_kernel(
    const float* __restrict__ x, const float* __restrict__ W,
    const float* __restrict__ bias, int which, int N)
{
    extern __shared__ float sm[];
    float* sW = sm;           // 128*128
    float* sX = sm + 16384;   // 64 rows * 132 (padded)

    int tid = threadIdx.x;
    for (int i = tid * 4; i < 16384; i += 1024)
        *reinterpret_cast<float4*>(&sW[i]) = *reinterpret_cast<const float4*>(&W[i]);

    int n0 = blockIdx.x * 64;
    for (int idx = tid; idx < 64 * 32; idx += 256) {
        int r = idx >> 5, c = (idx & 31) * 4;
        float4 v = make_float4(0.f, 0.f, 0.f, 0.f);
        if (n0 + r < N) v = *reinterpret_cast<const float4*>(&x[(n0 + r) * 128 + c]);
        *reinterpret_cast<float4*>(&sX[r * 132 + c]) = v;
    }
    __syncthreads();

    int og = tid & 15;   // 16 output groups of 8 cols
    int ng = tid >> 4;   // 16 row groups of 4 rows
    float acc[4][8];
#pragma unroll
    for (int e = 0; e < 4; e++)
#pragma unroll
        for (int o = 0; o < 8; o++) acc[e][o] = 0.f;

#pragma unroll 1
    for (int k = 0; k < 128; k += 4) {
        float4 hv[4];
#pragma unroll
        for (int e = 0; e < 4; e++)
            hv[e] = *reinterpret_cast<float4*>(&sX[(ng * 4 + e) * 132 + k]);
        float wv[4][8];
#pragma unroll
        for (int r = 0; r < 4; r++) {
            float4 w0 = *reinterpret_cast<float4*>(&sW[(k + r) * 128 + og * 8]);
            float4 w1 = *reinterpret_cast<float4*>(&sW[(k + r) * 128 + og * 8 + 4]);
            wv[r][0] = w0.x; wv[r][1] = w0.y; wv[r][2] = w0.z; wv[r][3] = w0.w;
            wv[r][4] = w1.x; wv[r][5] = w1.y; wv[r][6] = w1.z; wv[r][7] = w1.w;
        }
#pragma unroll
        for (int e = 0; e < 4; e++) {
            float hk[4] = {hv[e].x, hv[e].y, hv[e].z, hv[e].w};
#pragma unroll
            for (int r = 0; r < 4; r++)
#pragma unroll
                for (int o = 0; o < 8; o++)
                    acc[e][o] = fmaf(hk[r], wv[r][o], acc[e][o]);
        }
    }

    float bb[8];
#pragma unroll
    for (int o = 0; o < 8; o++) bb[o] = bias ? bias[og * 8 + o] : 0.f;

    float* outp = (which == 0) ? g_msg_src : ((which == 1) ? g_msg_tgt : g_skip);
#pragma unroll
    for (int e = 0; e < 4; e++) {
        int n = n0 + ng * 4 + e;
        if (n < N) {
            float4 r0 = make_float4(acc[e][0] + bb[0], acc[e][1] + bb[1],
                                    acc[e][2] + bb[2], acc[e][3] + bb[3]);
            float4 r1 = make_float4(acc[e][4] + bb[4], acc[e][5] + bb[5],
                                    acc[e][6] + bb[6], acc[e][7] + bb[7]);
            *reinterpret_cast<float4*>(&outp[n * 128 + og * 8]) = r0;
            *reinterpret_cast<float4*>(&outp[n * 128 + og * 8 + 4]) = r1;
        }
    }
}

__device__ __forceinline__ float prelu_f(float v, float a) {
    return v >= 0.f ? v : a * v;
}

// Persistent edge kernel: gather -> PReLU -> GEMM1 -> PReLU -> GEMM2 -> gate ->
// exp -> atomic accumulate (numerator + denominator) per target node.
__global__ void __launch_bounds__(256, 1) edge_kernel(
    const int* __restrict__ ei,   // int32! (JAX default disables x64)
    const float* __restrict__ W1, const float* __restrict__ b1,
    const float* __restrict__ W2, const float* __restrict__ b2,
    const float* __restrict__ Wg,
    const float* __restrict__ a0p, const float* __restrict__ a1p,
    int E)
{
    extern __shared__ float sm[];
    float* sW1 = sm;                       // 16384
    float* sW2 = sm + 16384;               // 16384
    float* sb1 = sm + 32768;               // 128
    float* sb2 = sb1 + 128;                // 128
    float* sWg = sb2 + 128;                // 128
    float* sH0 = sWg + 128;                // 64*132
    float* sH1 = sH0 + 64 * 132;           // 64*132
    int*   sJ  = reinterpret_cast<int*>(sH1 + 64 * 132);  // 64
    int*   sI  = sJ + 64;                                  // 64

    int tid = threadIdx.x;
    float a0 = *a0p, a1 = *a1p;

    for (int i = tid * 4; i < 16384; i += 1024) {
        *reinterpret_cast<float4*>(&sW1[i]) = *reinterpret_cast<const float4*>(&W1[i]);
        *reinterpret_cast<float4*>(&sW2[i]) = *reinterpret_cast<const float4*>(&W2[i]);
    }
    if (tid < 128) { sb1[tid] = b1[tid]; sb2[tid] = b2[tid]; sWg[tid] = Wg[tid]; }
    __syncthreads();

    int og = tid & 15;
    int eg = tid >> 4;
    int nTiles = (E + 63) >> 6;

    for (int tile = blockIdx.x; tile < nTiles; tile += gridDim.x) {
        int e0 = tile << 6;
        if (tid < 64) {
            int e = e0 + tid;
            sJ[tid] = (e < E) ? ei[e] : 0;
            sI[tid] = (e < E) ? ei[E + e] : 0;
        }
        __syncthreads();

        // gather: h0 = prelu(msg_src[j] + msg_tgt[i], a0)
        for (int idx = tid; idx < 64 * 32; idx += 256) {
            int e = idx >> 5, c = (idx & 31) * 4;
            float4 v = make_float4(0.f, 0.f, 0.f, 0.f);
            if (e0 + e < E) {
                float4 s = *reinterpret_cast<const float4*>(&g_msg_src[sJ[e] * 128 + c]);
                float4 t = *reinterpret_cast<const float4*>(&g_msg_tgt[sI[e] * 128 + c]);
                v.x = prelu_f(s.x + t.x, a0);
                v.y = prelu_f(s.y + t.y, a0);
                v.z = prelu_f(s.z + t.z, a0);
                v.w = prelu_f(s.w + t.w, a0);
            }
            *reinterpret_cast<float4*>(&sH0[e * 132 + c]) = v;
        }
        __syncthreads();

        // GEMM1: h1 = prelu(h0 @ W1 + b1, a1)
        float acc[4][8];
#pragma unroll
        for (int e = 0; e < 4; e++)
#pragma unroll
            for (int o = 0; o < 8; o++) acc[e][o] = 0.f;

#pragma unroll 1
        for (int k = 0; k < 128; k += 4) {
            float4 hv[4];
#pragma unroll
            for (int e = 0; e < 4; e++)
                hv[e] = *reinterpret_cast<float4*>(&sH0[(eg * 4 + e) * 132 + k]);
            float wv[4][8];
#pragma unroll
            for (int r = 0; r < 4; r++) {
                float4 w0 = *reinterpret_cast<float4*>(&sW1[(k + r) * 128 + og * 8]);
                float4 w1 = *reinterpret_cast<float4*>(&sW1[(k + r) * 128 + og * 8 + 4]);
                wv[r][0] = w0.x; wv[r][1] = w0.y; wv[r][2] = w0.z; wv[r][3] = w0.w;
                wv[r][4] = w1.x; wv[r][5] = w1.y; wv[r][6] = w1.z; wv[r][7] = w1.w;
            }
#pragma unroll
            for (int e = 0; e < 4; e++) {
                float hk[4] = {hv[e].x, hv[e].y, hv[e].z, hv[e].w};
#pragma unroll
                for (int r = 0; r < 4; r++)
#pragma unroll
                    for (int o = 0; o < 8; o++)
                        acc[e][o] = fmaf(hk[r], wv[r][o], acc[e][o]);
            }
        }

#pragma unroll
        for (int e = 0; e < 4; e++) {
            float4 r0, r1;
            r0.x = prelu_f(acc[e][0] + sb1[og * 8 + 0], a1);
            r0.y = prelu_f(acc[e][1] + sb1[og * 8 + 1], a1);
            r0.z = prelu_f(acc[e][2] + sb1[og * 8 + 2], a1);
            r0.w = prelu_f(acc[e][3] + sb1[og * 8 + 3], a1);
            r1.x = prelu_f(acc[e][4] + sb1[og * 8 + 4], a1);
            r1.y = prelu_f(acc[e][5] + sb1[og * 8 + 5], a1);
            r1.z = prelu_f(acc[e][6] + sb1[og * 8 + 6], a1);
            r1.w = prelu_f(acc[e][7] + sb1[og * 8 + 7], a1);
            *reinterpret_cast<float4*>(&sH1[(eg * 4 + e) * 132 + og * 8]) = r0;
            *reinterpret_cast<float4*>(&sH1[(eg * 4 + e) * 132 + og * 8 + 4]) = r1;
        }
        __syncthreads();

        // GEMM2: msg = h1 @ W2 + b2
        float acc2[4][8];
#pragma unroll
        for (int e = 0; e < 4; e++)
#pragma unroll
            for (int o = 0; o < 8; o++) acc2[e][o] = 0.f;

#pragma unroll 1
        for (int k = 0; k < 128; k += 4) {
            float4 hv[4];
#pragma unroll
            for (int e = 0; e < 4; e++)
                hv[e] = *reinterpret_cast<float4*>(&sH1[(eg * 4 + e) * 132 + k]);
            float wv[4][8];
#pragma unroll
            for (int r = 0; r < 4; r++) {
                float4 w0 = *reinterpret_cast<float4*>(&sW2[(k + r) * 128 + og * 8]);
                float4 w1 = *reinterpret_cast<float4*>(&sW2[(k + r) * 128 + og * 8 + 4]);
                wv[r][0] = w0.x; wv[r][1] = w0.y; wv[r][2] = w0.z; wv[r][3] = w0.w;
                wv[r][4] = w1.x; wv[r][5] = w1.y; wv[r][6] = w1.z; wv[r][7] = w1.w;
            }
#pragma unroll
            for (int e = 0; e < 4; e++) {
                float hk[4] = {hv[e].x, hv[e].y, hv[e].z, hv[e].w};
#pragma unroll
                for (int r = 0; r < 4; r++)
#pragma unroll
                    for (int o = 0; o < 8; o++)
                        acc2[e][o] = fmaf(hk[r], wv[r][o], acc2[e][o]);
            }
        }

        // gate partial over this thread's 8 columns, reduce across 16 og-lanes
        float part[4];
#pragma unroll
        for (int e = 0; e < 4; e++) {
            float p = 0.f;
#pragma unroll
            for (int o = 0; o < 8; o++) {
                acc2[e][o] += sb2[og * 8 + o];
                p = fmaf(acc2[e][o], sWg[og * 8 + o], p);
            }
            part[e] = p;
        }
#pragma unroll
        for (int off = 8; off; off >>= 1)
#pragma unroll
            for (int e = 0; e < 4; e++)
                part[e] += __shfl_xor_sync(0xffffffffu, part[e], off);

        // exp (shift-invariant softmax: max-subtraction unnecessary, gates O(1))
#pragma unroll
        for (int e = 0; e < 4; e++) {
            int le = eg * 4 + e;
            if (e0 + le < E) {
                float ex = expf(part[e]);
                int t = sI[le];
                float* base = &g_acc[t * 128 + og * 8];
#pragma unroll
                for (int o = 0; o < 8; o++) atomicAdd(base + o, ex * acc2[e][o]);
                if (og == 0) atomicAdd(&g_den[t], ex);
            }
        }
        __syncthreads();  // protect sH0/sH1/sI/sJ before next tile
    }
}

// Per-node: out = LayerNorm(acc/den + skip) * gamma + beta ; one warp per node
__global__ void __launch_bounds__(256) final_kernel(
    const float* __restrict__ gamma, const float* __restrict__ beta,
    float* __restrict__ out, int N)
{
    int node = (blockIdx.x * blockDim.x + threadIdx.x) >> 5;
    int lane = threadIdx.x & 31;
    if (node >= N) return;

    float4 a = *reinterpret_cast<const float4*>(&g_acc[node * 128 + lane * 4]);
    float4 s = *reinterpret_cast<const float4*>(&g_skip[node * 128 + lane * 4]);
    float dn = g_den[node];
    float inv = dn > 0.f ? 1.f / dn : 0.f;

    float v0 = fmaf(a.x, inv, s.x);
    float v1 = fmaf(a.y, inv, s.y);
    float v2 = fmaf(a.z, inv, s.z);
    float v3 = fmaf(a.w, inv, s.w);

    float sum = v0 + v1 + v2 + v3;
#pragma unroll
    for (int off = 16; off; off >>= 1) sum += __shfl_xor_sync(0xffffffffu, sum, off);
    float mu = sum * (1.f / 128.f);

    float d0 = v0 - mu, d1 = v1 - mu, d2 = v2 - mu, d3 = v3 - mu;
    float sq = d0 * d0 + d1 * d1 + d2 * d2 + d3 * d3;
#pragma unroll
    for (int off = 16; off; off >>= 1) sq += __shfl_xor_sync(0xffffffffu, sq, off);
    float rs = rsqrtf(sq * (1.f / 128.f) + 1e-5f);

    float4 g = *reinterpret_cast<const float4*>(&gamma[lane * 4]);
    float4 b = *reinterpret_cast<const float4*>(&beta[lane * 4]);
    float4 o;
    o.x = fmaf(d0 * rs, g.x, b.x);
    o.y = fmaf(d1 * rs, g.y, b.y);
    o.z = fmaf(d2 * rs, g.z, b.z);
    o.w = fmaf(d3 * rs, g.w, b.w);
    *reinterpret_cast<float4*>(&out[node * 128 + lane * 4]) = o;
}

extern "C" void kernel_launch(void* const* d_in, const int* in_sizes, int n_in,
                              void* d_out, int out_size)
{
    const float* x      = (const float*)d_in[0];
    const int*   ei     = (const int*)d_in[1];     // int32 edge_index
    const float* W_src  = (const float*)d_in[2];
    const float* b_src  = (const float*)d_in[3];
    const float* W_tgt  = (const float*)d_in[4];
    const float* W_skip = (const float*)d_in[5];
    const float* a0     = (const float*)d_in[6];
    const float* W1     = (const float*)d_in[7];
    const float* b1     = (const float*)d_in[8];
    const float* a1     = (const float*)d_in[9];
    const float* W2     = (const float*)d_in[10];
    const float* b2     = (const float*)d_in[11];
    const float* Wg     = (const float*)d_in[12];
    const float* gamma  = (const float*)d_in[13];
    const float* beta   = (const float*)d_in[14];
    float* out = (float*)d_out;

    int N = in_sizes[0] / 128;
    int E = in_sizes[1] / 2;

    const int NODE_SMEM = (16384 + 64 * 132) * 4;
    const int EDGE_SMEM = (16384 * 2 + 384 + 2 * 64 * 132) * 4 + 128 * 4;

    // One-time setup on first (non-capture) call; capture path is launches only.
    static int sms = 0;
    if (sms == 0) {
        cudaFuncSetAttribute(node_gemm_kernel, cudaFuncAttributeMaxDynamicSharedMemorySize, NODE_SMEM);
        cudaFuncSetAttribute(edge_kernel, cudaFuncAttributeMaxDynamicSharedMemorySize, EDGE_SMEM);
        int dev = 0, v = 148;
        cudaGetDevice(&dev);
        cudaDeviceGetAttribute(&v, cudaDevAttrMultiProcessorCount, dev);
        sms = (v > 0) ? v : 148;
    }

    zero_kernel<<<256, 256>>>(N);
    int nb = (N + 63) / 64;
    node_gemm_kernel<<<nb, 256, NODE_SMEM>>>(x, W_src, b_src, 0, N);
    node_gemm_kernel<<<nb, 256, NODE_SMEM>>>(x, W_tgt, nullptr, 1, N);
    node_gemm_kernel<<<nb, 256, NODE_SMEM>>>(x, W_skip, nullptr, 2, N);
    edge_kernel<<<sms, 256, EDGE_SMEM>>>(ei, W1, b1, W2, b2, Wg, a0, a1, E);
    final_kernel<<<(N * 32 + 255) / 256, 256>>>(gamma, beta, out, N);
}

// round 6
// speedup vs baseline: 2.7268x; 2.7268x over previous
#include <cuda_runtime.h>
#include <cstdint>

static const int NMAX = 20000;

// Scratch (device globals: no allocation allowed)
__device__ __align__(16) float g_msg_src[NMAX * 128];
__device__ __align__(16) float g_msg_tgt[NMAX * 128];
__device__ __align__(16) float g_skip[NMAX * 128];
__device__ __align__(16) float g_acc[NMAX * 128];
__device__ float g_den[NMAX];

__global__ void zero_kernel(int n) {
    float4 z = make_float4(0.f, 0.f, 0.f, 0.f);
    int stride = gridDim.x * blockDim.x;
    int tot4 = n * 32;
    for (int i = blockIdx.x * blockDim.x + threadIdx.x; i < tot4; i += stride)
        reinterpret_cast<float4*>(g_acc)[i] = z;
    for (int i = blockIdx.x * blockDim.x + threadIdx.x; i < n; i += stride)
        g_den[i] = 0.f;
}

// ---------------- node GEMM (FFMA, known-good from R2) ----------------
__global__ void __launch_bounds__(256, 1) node_gemm_kernel(
    const float* __restrict__ x, const float* __restrict__ W,
    const float* __restrict__ bias, int which, int N)
{
    extern __shared__ float sm[];
    float* sW = sm;           // 128*128
    float* sX = sm + 16384;   // 64 rows * 132

    int tid = threadIdx.x;
    for (int i = tid * 4; i < 16384; i += 1024)
        *reinterpret_cast<float4*>(&sW[i]) = *reinterpret_cast<const float4*>(&W[i]);

    int n0 = blockIdx.x * 64;
    for (int idx = tid; idx < 64 * 32; idx += 256) {
        int r = idx >> 5, c = (idx & 31) * 4;
        float4 v = make_float4(0.f, 0.f, 0.f, 0.f);
        if (n0 + r < N) v = *reinterpret_cast<const float4*>(&x[(n0 + r) * 128 + c]);
        *reinterpret_cast<float4*>(&sX[r * 132 + c]) = v;
    }
    __syncthreads();

    int og = tid & 15;
    int ng = tid >> 4;
    float acc[4][8];
#pragma unroll
    for (int e = 0; e < 4; e++)
#pragma unroll
        for (int o = 0; o < 8; o++) acc[e][o] = 0.f;

#pragma unroll 1
    for (int k = 0; k < 128; k += 4) {
        float4 hv[4];
#pragma unroll
        for (int e = 0; e < 4; e++)
            hv[e] = *reinterpret_cast<float4*>(&sX[(ng * 4 + e) * 132 + k]);
        float wv[4][8];
#pragma unroll
        for (int r = 0; r < 4; r++) {
            float4 w0 = *reinterpret_cast<float4*>(&sW[(k + r) * 128 + og * 8]);
            float4 w1 = *reinterpret_cast<float4*>(&sW[(k + r) * 128 + og * 8 + 4]);
            wv[r][0] = w0.x; wv[r][1] = w0.y; wv[r][2] = w0.z; wv[r][3] = w0.w;
            wv[r][4] = w1.x; wv[r][5] = w1.y; wv[r][6] = w1.z; wv[r][7] = w1.w;
        }
#pragma unroll
        for (int e = 0; e < 4; e++) {
            float hk[4] = {hv[e].x, hv[e].y, hv[e].z, hv[e].w};
#pragma unroll
            for (int r = 0; r < 4; r++)
#pragma unroll
                for (int o = 0; o < 8; o++)
                    acc[e][o] = fmaf(hk[r], wv[r][o], acc[e][o]);
        }
    }

    float bb[8];
#pragma unroll
    for (int o = 0; o < 8; o++) bb[o] = bias ? bias[og * 8 + o] : 0.f;

    float* outp = (which == 0) ? g_msg_src : ((which == 1) ? g_msg_tgt : g_skip);
#pragma unroll
    for (int e = 0; e < 4; e++) {
        int n = n0 + ng * 4 + e;
        if (n < N) {
            float4 r0 = make_float4(acc[e][0] + bb[0], acc[e][1] + bb[1],
                                    acc[e][2] + bb[2], acc[e][3] + bb[3]);
            float4 r1 = make_float4(acc[e][4] + bb[4], acc[e][5] + bb[5],
                                    acc[e][6] + bb[6], acc[e][7] + bb[7]);
            *reinterpret_cast<float4*>(&outp[n * 128 + og * 8]) = r0;
            *reinterpret_cast<float4*>(&outp[n * 128 + og * 8 + 4]) = r1;
        }
    }
}

// ---------------- helpers ----------------
__device__ __forceinline__ float prelu_f(float v, float a) {
    return v >= 0.f ? v : a * v;
}

__device__ __forceinline__ float to_tf32(float f) {
    uint32_t u;
    asm("cvt.rna.tf32.f32 %0, %1;" : "=r"(u) : "f"(f));
    return __uint_as_float(u);
}

__device__ __forceinline__ void mma_tf32(float* d, uint32_t a0, uint32_t a1,
                                         uint32_t a2, uint32_t a3,
                                         uint32_t b0, uint32_t b1) {
    float c0 = d[0], c1 = d[1], c2 = d[2], c3 = d[3];
    asm volatile(
        "mma.sync.aligned.m16n8k8.row.col.f32.tf32.tf32.f32 "
        "{%0,%1,%2,%3}, {%4,%5,%6,%7}, {%8,%9}, {%10,%11,%12,%13};\n"
        : "=f"(d[0]), "=f"(d[1]), "=f"(d[2]), "=f"(d[3])
        : "r"(a0), "r"(a1), "r"(a2), "r"(a3), "r"(b0), "r"(b1),
          "f"(c0), "f"(c1), "f"(c2), "f"(c3));
}

// ---------------- edge kernel (tf32 tensor-core MLP) ----------------
// smem (floats): sW1 17408 | sW2 17408 | sH0 8448 | sH1 8448 |
//                sb1 128 | sb2 128 | sWg 128 | sGP 256 | sJ+sI 128 ints
// total = 52480 floats = 209920 bytes
static const int EDGE_SMEM_FLOATS = 17408 * 2 + 8448 * 2 + 384 + 256 + 128;

__global__ void __launch_bounds__(256, 1) edge_kernel(
    const int* __restrict__ ei,
    const float* __restrict__ W1, const float* __restrict__ b1,
    const float* __restrict__ W2, const float* __restrict__ b2,
    const float* __restrict__ Wg,
    const float* __restrict__ a0p, const float* __restrict__ a1p,
    int E, int N)
{
    extern __shared__ float sm[];
    float* sW1 = sm;
    float* sW2 = sm + 17408;
    float* sH0 = sm + 34816;
    float* sH1 = sm + 43264;
    float* sb1 = sm + 51712;
    float* sb2 = sb1 + 128;
    float* sWg = sb2 + 128;
    float* sGP = sWg + 128;                 // [2][64], padded region of 256
    int*   sJ  = reinterpret_cast<int*>(sGP + 256);   // 64 ints
    int*   sI  = sJ + 64;                              // 64 ints

    int tid = threadIdx.x;
    int w    = tid >> 5;
    int lane = tid & 31;
    int g    = lane >> 2;       // groupID 0..7
    int tig  = lane & 3;        // thread-in-group 0..3
    int m0   = (w & 3) * 16;    // edge-row base for this warp
    int nbase = (w >> 2) * 64;  // column half

    float a0 = *a0p, a1 = *a1p;

    // weights -> tf32, stride 136 (conflict-free B frags)
    for (int idx = tid; idx < 16384; idx += 256) {
        int k = idx >> 7, n = idx & 127;
        sW1[k * 136 + n] = to_tf32(W1[idx]);
        sW2[k * 136 + n] = to_tf32(W2[idx]);
    }
    if (tid < 128) { sb1[tid] = b1[tid]; sb2[tid] = b2[tid]; sWg[tid] = Wg[tid]; }
    __syncthreads();

    int nTiles = (E + 63) >> 6;

    for (int tile = blockIdx.x; tile < nTiles; tile += gridDim.x) {
        int e0 = tile << 6;
        if (tid < 64) {
            int e = e0 + tid;
            int j = 0, i = 0;
            if (e < E) { j = ei[e]; i = ei[E + e]; }
            j = (j < 0) ? 0 : (j >= N ? N - 1 : j);
            i = (i < 0) ? 0 : (i >= N ? N - 1 : i);
            sJ[tid] = j;
            sI[tid] = i;
        }
        __syncthreads();

        // gather: h0 = tf32(prelu(msg_src[j] + msg_tgt[i], a0))
        for (int idx = tid; idx < 64 * 32; idx += 256) {
            int e = idx >> 5, c = (idx & 31) * 4;
            float4 v = make_float4(0.f, 0.f, 0.f, 0.f);
            if (e0 + e < E) {
                float4 s = *reinterpret_cast<const float4*>(&g_msg_src[sJ[e] * 128 + c]);
                float4 t = *reinterpret_cast<const float4*>(&g_msg_tgt[sI[e] * 128 + c]);
                v.x = to_tf32(prelu_f(s.x + t.x, a0));
                v.y = to_tf32(prelu_f(s.y + t.y, a0));
                v.z = to_tf32(prelu_f(s.z + t.z, a0));
                v.w = to_tf32(prelu_f(s.w + t.w, a0));
            }
            *reinterpret_cast<float4*>(&sH0[e * 132 + c]) = v;
        }
        __syncthreads();

        // ---- GEMM1: h1 = prelu(h0 @ W1 + b1, a1) ----
        float acc[8][4];
#pragma unroll
        for (int nt = 0; nt < 8; nt++)
#pragma unroll
            for (int c = 0; c < 4; c++) acc[nt][c] = 0.f;

#pragma unroll 1
        for (int k0 = 0; k0 < 128; k0 += 8) {
            uint32_t A0 = __float_as_uint(sH0[(m0 + g) * 132 + k0 + tig]);
            uint32_t A1 = __float_as_uint(sH0[(m0 + g + 8) * 132 + k0 + tig]);
            uint32_t A2 = __float_as_uint(sH0[(m0 + g) * 132 + k0 + tig + 4]);
            uint32_t A3 = __float_as_uint(sH0[(m0 + g + 8) * 132 + k0 + tig + 4]);
#pragma unroll
            for (int nt = 0; nt < 8; nt++) {
                int n0 = nbase + nt * 8;
                uint32_t B0 = __float_as_uint(sW1[(k0 + tig) * 136 + n0 + g]);
                uint32_t B1 = __float_as_uint(sW1[(k0 + tig + 4) * 136 + n0 + g]);
                mma_tf32(acc[nt], A0, A1, A2, A3, B0, B1);
            }
        }

        // epilogue 1: bias + prelu + tf32 store to sH1
#pragma unroll
        for (int nt = 0; nt < 8; nt++) {
            int c0 = nbase + nt * 8 + 2 * tig;
            sH1[(m0 + g) * 132 + c0]     = to_tf32(prelu_f(acc[nt][0] + sb1[c0], a1));
            sH1[(m0 + g) * 132 + c0 + 1] = to_tf32(prelu_f(acc[nt][1] + sb1[c0 + 1], a1));
            sH1[(m0 + g + 8) * 132 + c0]     = to_tf32(prelu_f(acc[nt][2] + sb1[c0], a1));
            sH1[(m0 + g + 8) * 132 + c0 + 1] = to_tf32(prelu_f(acc[nt][3] + sb1[c0 + 1], a1));
        }
        __syncthreads();

        // ---- GEMM2: msg = h1 @ W2 + b2 ----
        float acc2[8][4];
#pragma unroll
        for (int nt = 0; nt < 8; nt++)
#pragma unroll
            for (int c = 0; c < 4; c++) acc2[nt][c] = 0.f;

#pragma unroll 1
        for (int k0 = 0; k0 < 128; k0 += 8) {
            uint32_t A0 = __float_as_uint(sH1[(m0 + g) * 132 + k0 + tig]);
            uint32_t A1 = __float_as_uint(sH1[(m0 + g + 8) * 132 + k0 + tig]);
            uint32_t A2 = __float_as_uint(sH1[(m0 + g) * 132 + k0 + tig + 4]);
            uint32_t A3 = __float_as_uint(sH1[(m0 + g + 8) * 132 + k0 + tig + 4]);
#pragma unroll
            for (int nt = 0; nt < 8; nt++) {
                int n0 = nbase + nt * 8;
                uint32_t B0 = __float_as_uint(sW2[(k0 + tig) * 136 + n0 + g]);
                uint32_t B1 = __float_as_uint(sW2[(k0 + tig + 4) * 136 + n0 + g]);
                mma_tf32(acc2[nt], A0, A1, A2, A3, B0, B1);
            }
        }

        // add b2; gate partials over this warp's 64 cols
        float p0 = 0.f, p1 = 0.f;
#pragma unroll
        for (int nt = 0; nt < 8; nt++) {
            int c0 = nbase + nt * 8 + 2 * tig;
            acc2[nt][0] += sb2[c0];
            acc2[nt][1] += sb2[c0 + 1];
            acc2[nt][2] += sb2[c0];
            acc2[nt][3] += sb2[c0 + 1];
            p0 = fmaf(acc2[nt][0], sWg[c0], p0);
            p0 = fmaf(acc2[nt][1], sWg[c0 + 1], p0);
            p1 = fmaf(acc2[nt][2], sWg[c0], p1);
            p1 = fmaf(acc2[nt][3], sWg[c0 + 1], p1);
        }
        p0 += __shfl_xor_sync(0xffffffffu, p0, 1);
        p0 += __shfl_xor_sync(0xffffffffu, p0, 2);
        p1 += __shfl_xor_sync(0xffffffffu, p1, 1);
        p1 += __shfl_xor_sync(0xffffffffu, p1, 2);
        if (tig == 0) {
            sGP[(w >> 2) * 64 + m0 + g] = p0;
            sGP[(w >> 2) * 64 + m0 + 8 + g] = p1;
        }
        __syncthreads();

        // exp + atomic accumulate (shift-invariant softmax)
        int r0 = m0 + g, r1 = m0 + g + 8;
        float ex0 = expf(sGP[r0] + sGP[64 + r0]);
        float ex1 = expf(sGP[r1] + sGP[64 + r1]);
        bool ok0 = (e0 + r0 < E), ok1 = (e0 + r1 < E);
        int t0 = sI[r0], t1 = sI[r1];
        if (ok0) {
            float* base = &g_acc[t0 * 128];
#pragma unroll
            for (int nt = 0; nt < 8; nt++) {
                int c0 = nbase + nt * 8 + 2 * tig;
                atomicAdd(base + c0, ex0 * acc2[nt][0]);
                atomicAdd(base + c0 + 1, ex0 * acc2[nt][1]);
            }
        }
        if (ok1) {
            float* base = &g_acc[t1 * 128];
#pragma unroll
            for (int nt = 0; nt < 8; nt++) {
                int c0 = nbase + nt * 8 + 2 * tig;
                atomicAdd(base + c0, ex1 * acc2[nt][2]);
                atomicAdd(base + c0 + 1, ex1 * acc2[nt][3]);
            }
        }
        if ((w >> 2) == 0 && tig == 0) {
            if (ok0) atomicAdd(&g_den[t0], ex0);
            if (ok1) atomicAdd(&g_den[t1], ex1);
        }
        __syncthreads();  // protect smem before next tile
    }
}

// ---------------- final per-node kernel ----------------
__global__ void __launch_bounds__(256) final_kernel(
    const float* __restrict__ gamma, const float* __restrict__ beta,
    float* __restrict__ out, int N)
{
    int node = (blockIdx.x * blockDim.x + threadIdx.x) >> 5;
    int lane = threadIdx.x & 31;
    if (node >= N) return;

    float4 a = *reinterpret_cast<const float4*>(&g_acc[node * 128 + lane * 4]);
    float4 s = *reinterpret_cast<const float4*>(&g_skip[node * 128 + lane * 4]);
    float dn = g_den[node];
    float inv = dn > 0.f ? 1.f / dn : 0.f;

    float v0 = fmaf(a.x, inv, s.x);
    float v1 = fmaf(a.y, inv, s.y);
    float v2 = fmaf(a.z, inv, s.z);
    float v3 = fmaf(a.w, inv, s.w);

    float sum = v0 + v1 + v2 + v3;
#pragma unroll
    for (int off = 16; off; off >>= 1) sum += __shfl_xor_sync(0xffffffffu, sum, off);
    float mu = sum * (1.f / 128.f);

    float d0 = v0 - mu, d1 = v1 - mu, d2 = v2 - mu, d3 = v3 - mu;
    float sq = d0 * d0 + d1 * d1 + d2 * d2 + d3 * d3;
#pragma unroll
    for (int off = 16; off; off >>= 1) sq += __shfl_xor_sync(0xffffffffu, sq, off);
    float rs = rsqrtf(sq * (1.f / 128.f) + 1e-5f);

    float4 gm = *reinterpret_cast<const float4*>(&gamma[lane * 4]);
    float4 bt = *reinterpret_cast<const float4*>(&beta[lane * 4]);
    float4 o;
    o.x = fmaf(d0 * rs, gm.x, bt.x);
    o.y = fmaf(d1 * rs, gm.y, bt.y);
    o.z = fmaf(d2 * rs, gm.z, bt.z);
    o.w = fmaf(d3 * rs, gm.w, bt.w);
    *reinterpret_cast<float4*>(&out[node * 128 + lane * 4]) = o;
}

extern "C" void kernel_launch(void* const* d_in, const int* in_sizes, int n_in,
                              void* d_out, int out_size)
{
    const float* x      = (const float*)d_in[0];
    const int*   ei     = (const int*)d_in[1];
    const float* W_src  = (const float*)d_in[2];
    const float* b_src  = (const float*)d_in[3];
    const float* W_tgt  = (const float*)d_in[4];
    const float* W_skip = (const float*)d_in[5];
    const float* a0     = (const float*)d_in[6];
    const float* W1     = (const float*)d_in[7];
    const float* b1     = (const float*)d_in[8];
    const float* a1     = (const float*)d_in[9];
    const float* W2     = (const float*)d_in[10];
    const float* b2     = (const float*)d_in[11];
    const float* Wg     = (const float*)d_in[12];
    const float* gamma  = (const float*)d_in[13];
    const float* beta   = (const float*)d_in[14];
    float* out = (float*)d_out;

    int N = in_sizes[0] / 128;
    int E = in_sizes[1] / 2;

    const int NODE_SMEM = (16384 + 64 * 132) * 4;
    const int EDGE_SMEM = EDGE_SMEM_FLOATS * 4;

    static int sms = 0;
    if (sms == 0) {
        cudaFuncSetAttribute(node_gemm_kernel, cudaFuncAttributeMaxDynamicSharedMemorySize, NODE_SMEM);
        cudaFuncSetAttribute(edge_kernel, cudaFuncAttributeMaxDynamicSharedMemorySize, EDGE_SMEM);
        int dev = 0, v = 148;
        cudaGetDevice(&dev);
        cudaDeviceGetAttribute(&v, cudaDevAttrMultiProcessorCount, dev);
        sms = (v > 0) ? v : 148;
    }

    zero_kernel<<<256, 256>>>(N);
    int nb = (N + 63) / 64;
    node_gemm_kernel<<<nb, 256, NODE_SMEM>>>(x, W_src, b_src, 0, N);
    node_gemm_kernel<<<nb, 256, NODE_SMEM>>>(x, W_tgt, nullptr, 1, N);
    node_gemm_kernel<<<nb, 256, NODE_SMEM>>>(x, W_skip, nullptr, 2, N);
    edge_kernel<<<sms, 256, EDGE_SMEM>>>(ei, W1, b1, W2, b2, Wg, a0, a1, E, N);
    final_kernel<<<(N * 32 + 255) / 256, 256>>>(gamma, beta, out, N);
}

// round 7
// speedup vs baseline: 2.9177x; 1.0700x over previous
#include <cuda_runtime.h>
#include <cstdint>

static const int NMAX = 20000;

// Scratch (device globals: no allocation allowed)
__device__ __align__(16) float g_msg_src[NMAX * 128];
__device__ __align__(16) float g_msg_tgt[NMAX * 128];
__device__ __align__(16) float g_skip[NMAX * 128];
__device__ __align__(16) float g_acc[NMAX * 128];
__device__ float g_den[NMAX];

__global__ void zero_kernel(int n) {
    float4 z = make_float4(0.f, 0.f, 0.f, 0.f);
    int stride = gridDim.x * blockDim.x;
    int tot4 = n * 32;
    for (int i = blockIdx.x * blockDim.x + threadIdx.x; i < tot4; i += stride)
        reinterpret_cast<float4*>(g_acc)[i] = z;
    for (int i = blockIdx.x * blockDim.x + threadIdx.x; i < n; i += stride)
        g_den[i] = 0.f;
}

// ---------------- fused node GEMM: x loaded once, 3 weights looped ----------------
__global__ void __launch_bounds__(256, 1) node3_kernel(
    const float* __restrict__ x,
    const float* __restrict__ W_src, const float* __restrict__ b_src,
    const float* __restrict__ W_tgt, const float* __restrict__ W_skip,
    int N)
{
    extern __shared__ float sm[];
    float* sW = sm;           // 128*128
    float* sX = sm + 16384;   // 64 rows * 132

    int tid = threadIdx.x;
    int n0 = blockIdx.x * 64;

    // x tile loaded ONCE
    for (int idx = tid; idx < 64 * 32; idx += 256) {
        int r = idx >> 5, c = (idx & 31) * 4;
        float4 v = make_float4(0.f, 0.f, 0.f, 0.f);
        if (n0 + r < N) v = *reinterpret_cast<const float4*>(&x[(n0 + r) * 128 + c]);
        *reinterpret_cast<float4*>(&sX[r * 132 + c]) = v;
    }

    int og = tid & 15;
    int ng = tid >> 4;

#pragma unroll 1
    for (int which = 0; which < 3; which++) {
        const float* W = (which == 0) ? W_src : ((which == 1) ? W_tgt : W_skip);
        __syncthreads();  // protect sW reuse (and sX on first iter)
        for (int i = tid * 4; i < 16384; i += 1024)
            *reinterpret_cast<float4*>(&sW[i]) = *reinterpret_cast<const float4*>(&W[i]);
        __syncthreads();

        float acc[4][8];
#pragma unroll
        for (int e = 0; e < 4; e++)
#pragma unroll
            for (int o = 0; o < 8; o++) acc[e][o] = 0.f;

#pragma unroll 1
        for (int k = 0; k < 128; k += 4) {
            float4 hv[4];
#pragma unroll
            for (int e = 0; e < 4; e++)
                hv[e] = *reinterpret_cast<float4*>(&sX[(ng * 4 + e) * 132 + k]);
            float wv[4][8];
#pragma unroll
            for (int r = 0; r < 4; r++) {
                float4 w0 = *reinterpret_cast<float4*>(&sW[(k + r) * 128 + og * 8]);
                float4 w1 = *reinterpret_cast<float4*>(&sW[(k + r) * 128 + og * 8 + 4]);
                wv[r][0] = w0.x; wv[r][1] = w0.y; wv[r][2] = w0.z; wv[r][3] = w0.w;
                wv[r][4] = w1.x; wv[r][5] = w1.y; wv[r][6] = w1.z; wv[r][7] = w1.w;
            }
#pragma unroll
            for (int e = 0; e < 4; e++) {
                float hk[4] = {hv[e].x, hv[e].y, hv[e].z, hv[e].w};
#pragma unroll
                for (int r = 0; r < 4; r++)
#pragma unroll
                    for (int o = 0; o < 8; o++)
                        acc[e][o] = fmaf(hk[r], wv[r][o], acc[e][o]);
            }
        }

        float bb[8];
#pragma unroll
        for (int o = 0; o < 8; o++) bb[o] = (which == 0) ? b_src[og * 8 + o] : 0.f;

        float* outp = (which == 0) ? g_msg_src : ((which == 1) ? g_msg_tgt : g_skip);
#pragma unroll
        for (int e = 0; e < 4; e++) {
            int n = n0 + ng * 4 + e;
            if (n < N) {
                float4 r0 = make_float4(acc[e][0] + bb[0], acc[e][1] + bb[1],
                                        acc[e][2] + bb[2], acc[e][3] + bb[3]);
                float4 r1 = make_float4(acc[e][4] + bb[4], acc[e][5] + bb[5],
                                        acc[e][6] + bb[6], acc[e][7] + bb[7]);
                *reinterpret_cast<float4*>(&outp[n * 128 + og * 8]) = r0;
                *reinterpret_cast<float4*>(&outp[n * 128 + og * 8 + 4]) = r1;
            }
        }
    }
}

// ---------------- helpers ----------------
__device__ __forceinline__ float prelu_f(float v, float a) {
    return v >= 0.f ? v : a * v;
}

__device__ __forceinline__ float to_tf32(float f) {
    uint32_t u;
    asm("cvt.rna.tf32.f32 %0, %1;" : "=r"(u) : "f"(f));
    return __uint_as_float(u);
}

__device__ __forceinline__ void mma_tf32(float* d, uint32_t a0, uint32_t a1,
                                         uint32_t a2, uint32_t a3,
                                         uint32_t b0, uint32_t b1) {
    float c0 = d[0], c1 = d[1], c2 = d[2], c3 = d[3];
    asm volatile(
        "mma.sync.aligned.m16n8k8.row.col.f32.tf32.tf32.f32 "
        "{%0,%1,%2,%3}, {%4,%5,%6,%7}, {%8,%9}, {%10,%11,%12,%13};\n"
        : "=f"(d[0]), "=f"(d[1]), "=f"(d[2]), "=f"(d[3])
        : "r"(a0), "r"(a1), "r"(a2), "r"(a3), "r"(b0), "r"(b1),
          "f"(c0), "f"(c1), "f"(c2), "f"(c3));
}

// ---------------- edge kernel (tf32, 32x32 warp tiles) ----------------
// smem (floats): sW1 17408 | sW2 17408 | sH0 8448 | sH1 8448 |
//                sb1 128 | sb2 128 | sWg 128 | sGP 256 | sJ+sI 128 ints
// total = 52480 floats = 209920 bytes
static const int EDGE_SMEM_FLOATS = 17408 * 2 + 8448 * 2 + 384 + 256 + 128;

__global__ void __launch_bounds__(256, 1) edge_kernel(
    const int* __restrict__ ei,
    const float* __restrict__ W1, const float* __restrict__ b1,
    const float* __restrict__ W2, const float* __restrict__ b2,
    const float* __restrict__ Wg,
    const float* __restrict__ a0p, const float* __restrict__ a1p,
    int E, int N)
{
    extern __shared__ float sm[];
    float* sW1 = sm;
    float* sW2 = sm + 17408;
    float* sH0 = sm + 34816;
    float* sH1 = sm + 43264;
    float* sb1 = sm + 51712;
    float* sb2 = sb1 + 128;
    float* sWg = sb2 + 128;
    float* sGP = sWg + 128;                 // [4][64]
    int*   sJ  = reinterpret_cast<int*>(sGP + 256);   // 64 ints
    int*   sI  = sJ + 64;                              // 64 ints

    int tid = threadIdx.x;
    int w    = tid >> 5;
    int lane = tid & 31;
    int g    = lane >> 2;       // groupID 0..7
    int tig  = lane & 3;        // thread-in-group 0..3
    int m0   = (w & 1) * 32;    // row base (2-way row split)
    int cg   = w >> 1;          // column group 0..3
    int nbase = cg * 32;        // 32 cols per warp

    float a0 = *a0p, a1 = *a1p;

    // weights -> tf32, stride 136 (conflict-free B frags)
    for (int idx = tid; idx < 16384; idx += 256) {
        int k = idx >> 7, n = idx & 127;
        sW1[k * 136 + n] = to_tf32(W1[idx]);
        sW2[k * 136 + n] = to_tf32(W2[idx]);
    }
    if (tid < 128) { sb1[tid] = b1[tid]; sb2[tid] = b2[tid]; sWg[tid] = Wg[tid]; }
    __syncthreads();

    int nTiles = (E + 63) >> 6;

    for (int tile = blockIdx.x; tile < nTiles; tile += gridDim.x) {
        int e0 = tile << 6;
        if (tid < 64) {
            int e = e0 + tid;
            int j = 0, i = 0;
            if (e < E) { j = ei[e]; i = ei[E + e]; }
            j = (j < 0) ? 0 : (j >= N ? N - 1 : j);
            i = (i < 0) ? 0 : (i >= N ? N - 1 : i);
            sJ[tid] = j;
            sI[tid] = i;
        }
        __syncthreads();

        // gather: h0 = tf32(prelu(msg_src[j] + msg_tgt[i], a0))
        for (int idx = tid; idx < 64 * 32; idx += 256) {
            int e = idx >> 5, c = (idx & 31) * 4;
            float4 v = make_float4(0.f, 0.f, 0.f, 0.f);
            if (e0 + e < E) {
                float4 s = *reinterpret_cast<const float4*>(&g_msg_src[sJ[e] * 128 + c]);
                float4 t = *reinterpret_cast<const float4*>(&g_msg_tgt[sI[e] * 128 + c]);
                v.x = to_tf32(prelu_f(s.x + t.x, a0));
                v.y = to_tf32(prelu_f(s.y + t.y, a0));
                v.z = to_tf32(prelu_f(s.z + t.z, a0));
                v.w = to_tf32(prelu_f(s.w + t.w, a0));
            }
            *reinterpret_cast<float4*>(&sH0[e * 132 + c]) = v;
        }
        __syncthreads();

        // ---- GEMM1: h1 = prelu(h0 @ W1 + b1, a1) ----
        float acc[2][4][4];
#pragma unroll
        for (int mb = 0; mb < 2; mb++)
#pragma unroll
            for (int nt = 0; nt < 4; nt++)
#pragma unroll
                for (int c = 0; c < 4; c++) acc[mb][nt][c] = 0.f;

#pragma unroll 1
        for (int k0 = 0; k0 < 128; k0 += 8) {
            uint32_t A[2][4];
#pragma unroll
            for (int mb = 0; mb < 2; mb++) {
                int br = m0 + mb * 16;
                A[mb][0] = __float_as_uint(sH0[(br + g) * 132 + k0 + tig]);
                A[mb][1] = __float_as_uint(sH0[(br + g + 8) * 132 + k0 + tig]);
                A[mb][2] = __float_as_uint(sH0[(br + g) * 132 + k0 + tig + 4]);
                A[mb][3] = __float_as_uint(sH0[(br + g + 8) * 132 + k0 + tig + 4]);
            }
#pragma unroll
            for (int nt = 0; nt < 4; nt++) {
                int n0 = nbase + nt * 8;
                uint32_t B0 = __float_as_uint(sW1[(k0 + tig) * 136 + n0 + g]);
                uint32_t B1 = __float_as_uint(sW1[(k0 + tig + 4) * 136 + n0 + g]);
#pragma unroll
                for (int mb = 0; mb < 2; mb++)
                    mma_tf32(acc[mb][nt], A[mb][0], A[mb][1], A[mb][2], A[mb][3], B0, B1);
            }
        }

        // epilogue 1: bias + prelu + tf32 store to sH1
#pragma unroll
        for (int mb = 0; mb < 2; mb++) {
            int br = m0 + mb * 16;
#pragma unroll
            for (int nt = 0; nt < 4; nt++) {
                int c0 = nbase + nt * 8 + 2 * tig;
                sH1[(br + g) * 132 + c0]     = to_tf32(prelu_f(acc[mb][nt][0] + sb1[c0], a1));
                sH1[(br + g) * 132 + c0 + 1] = to_tf32(prelu_f(acc[mb][nt][1] + sb1[c0 + 1], a1));
                sH1[(br + g + 8) * 132 + c0]     = to_tf32(prelu_f(acc[mb][nt][2] + sb1[c0], a1));
                sH1[(br + g + 8) * 132 + c0 + 1] = to_tf32(prelu_f(acc[mb][nt][3] + sb1[c0 + 1], a1));
            }
        }
        __syncthreads();

        // ---- GEMM2: msg = h1 @ W2 + b2 ----
        float acc2[2][4][4];
#pragma unroll
        for (int mb = 0; mb < 2; mb++)
#pragma unroll
            for (int nt = 0; nt < 4; nt++)
#pragma unroll
                for (int c = 0; c < 4; c++) acc2[mb][nt][c] = 0.f;

#pragma unroll 1
        for (int k0 = 0; k0 < 128; k0 += 8) {
            uint32_t A[2][4];
#pragma unroll
            for (int mb = 0; mb < 2; mb++) {
                int br = m0 + mb * 16;
                A[mb][0] = __float_as_uint(sH1[(br + g) * 132 + k0 + tig]);
                A[mb][1] = __float_as_uint(sH1[(br + g + 8) * 132 + k0 + tig]);
                A[mb][2] = __float_as_uint(sH1[(br + g) * 132 + k0 + tig + 4]);
                A[mb][3] = __float_as_uint(sH1[(br + g + 8) * 132 + k0 + tig + 4]);
            }
#pragma unroll
            for (int nt = 0; nt < 4; nt++) {
                int n0 = nbase + nt * 8;
                uint32_t B0 = __float_as_uint(sW2[(k0 + tig) * 136 + n0 + g]);
                uint32_t B1 = __float_as_uint(sW2[(k0 + tig + 4) * 136 + n0 + g]);
#pragma unroll
                for (int mb = 0; mb < 2; mb++)
                    mma_tf32(acc2[mb][nt], A[mb][0], A[mb][1], A[mb][2], A[mb][3], B0, B1);
            }
        }

        // add b2; gate partials over this warp's 32 cols
        float p[2][2] = {{0.f, 0.f}, {0.f, 0.f}};
#pragma unroll
        for (int mb = 0; mb < 2; mb++)
#pragma unroll
            for (int nt = 0; nt < 4; nt++) {
                int c0 = nbase + nt * 8 + 2 * tig;
                acc2[mb][nt][0] += sb2[c0];
                acc2[mb][nt][1] += sb2[c0 + 1];
                acc2[mb][nt][2] += sb2[c0];
                acc2[mb][nt][3] += sb2[c0 + 1];
                p[mb][0] = fmaf(acc2[mb][nt][0], sWg[c0], p[mb][0]);
                p[mb][0] = fmaf(acc2[mb][nt][1], sWg[c0 + 1], p[mb][0]);
                p[mb][1] = fmaf(acc2[mb][nt][2], sWg[c0], p[mb][1]);
                p[mb][1] = fmaf(acc2[mb][nt][3], sWg[c0 + 1], p[mb][1]);
            }
#pragma unroll
        for (int mb = 0; mb < 2; mb++) {
#pragma unroll
            for (int half = 0; half < 2; half++) {
                p[mb][half] += __shfl_xor_sync(0xffffffffu, p[mb][half], 1);
                p[mb][half] += __shfl_xor_sync(0xffffffffu, p[mb][half], 2);
            }
        }
        if (tig == 0) {
#pragma unroll
            for (int mb = 0; mb < 2; mb++) {
                sGP[cg * 64 + m0 + mb * 16 + g] = p[mb][0];
                sGP[cg * 64 + m0 + mb * 16 + 8 + g] = p[mb][1];
            }
        }
        __syncthreads();

        // exp + atomic accumulate (shift-invariant softmax)
#pragma unroll
        for (int mb = 0; mb < 2; mb++) {
#pragma unroll
            for (int half = 0; half < 2; half++) {
                int r = m0 + mb * 16 + half * 8 + g;
                if (e0 + r < E) {
                    float gate = sGP[r] + sGP[64 + r] + sGP[128 + r] + sGP[192 + r];
                    float ex = expf(gate);
                    int t = sI[r];
                    float* base = &g_acc[t * 128];
#pragma unroll
                    for (int nt = 0; nt < 4; nt++) {
                        int c0 = nbase + nt * 8 + 2 * tig;
                        atomicAdd(base + c0, ex * acc2[mb][nt][half * 2]);
                        atomicAdd(base + c0 + 1, ex * acc2[mb][nt][half * 2 + 1]);
                    }
                    if (cg == 0 && tig == 0) atomicAdd(&g_den[t], ex);
                }
            }
        }
        __syncthreads();  // protect smem before next tile
    }
}

// ---------------- final per-node kernel ----------------
__global__ void __launch_bounds__(256) final_kernel(
    const float* __restrict__ gamma, const float* __restrict__ beta,
    float* __restrict__ out, int N)
{
    int node = (blockIdx.x * blockDim.x + threadIdx.x) >> 5;
    int lane = threadIdx.x & 31;
    if (node >= N) return;

    float4 a = *reinterpret_cast<const float4*>(&g_acc[node * 128 + lane * 4]);
    float4 s = *reinterpret_cast<const float4*>(&g_skip[node * 128 + lane * 4]);
    float dn = g_den[node];
    float inv = dn > 0.f ? 1.f / dn : 0.f;

    float v0 = fmaf(a.x, inv, s.x);
    float v1 = fmaf(a.y, inv, s.y);
    float v2 = fmaf(a.z, inv, s.z);
    float v3 = fmaf(a.w, inv, s.w);

    float sum = v0 + v1 + v2 + v3;
#pragma unroll
    for (int off = 16; off; off >>= 1) sum += __shfl_xor_sync(0xffffffffu, sum, off);
    float mu = sum * (1.f / 128.f);

    float d0 = v0 - mu, d1 = v1 - mu, d2 = v2 - mu, d3 = v3 - mu;
    float sq = d0 * d0 + d1 * d1 + d2 * d2 + d3 * d3;
#pragma unroll
    for (int off = 16; off; off >>= 1) sq += __shfl_xor_sync(0xffffffffu, sq, off);
    float rs = rsqrtf(sq * (1.f / 128.f) + 1e-5f);

    float4 gm = *reinterpret_cast<const float4*>(&gamma[lane * 4]);
    float4 bt = *reinterpret_cast<const float4*>(&beta[lane * 4]);
    float4 o;
    o.x = fmaf(d0 * rs, gm.x, bt.x);
    o.y = fmaf(d1 * rs, gm.y, bt.y);
    o.z = fmaf(d2 * rs, gm.z, bt.z);
    o.w = fmaf(d3 * rs, gm.w, bt.w);
    *reinterpret_cast<float4*>(&out[node * 128 + lane * 4]) = o;
}

extern "C" void kernel_launch(void* const* d_in, const int* in_sizes, int n_in,
                              void* d_out, int out_size)
{
    const float* x      = (const float*)d_in[0];
    const int*   ei     = (const int*)d_in[1];
    const float* W_src  = (const float*)d_in[2];
    const float* b_src  = (const float*)d_in[3];
    const float* W_tgt  = (const float*)d_in[4];
    const float* W_skip = (const float*)d_in[5];
    const float* a0     = (const float*)d_in[6];
    const float* W1     = (const float*)d_in[7];
    const float* b1     = (const float*)d_in[8];
    const float* a1     = (const float*)d_in[9];
    const float* W2     = (const float*)d_in[10];
    const float* b2     = (const float*)d_in[11];
    const float* Wg     = (const float*)d_in[12];
    const float* gamma  = (const float*)d_in[13];
    const float* beta   = (const float*)d_in[14];
    float* out = (float*)d_out;

    int N = in_sizes[0] / 128;
    int E = in_sizes[1] / 2;

    const int NODE_SMEM = (16384 + 64 * 132) * 4;
    const int EDGE_SMEM = EDGE_SMEM_FLOATS * 4;

    static int sms = 0;
    if (sms == 0) {
        cudaFuncSetAttribute(node3_kernel, cudaFuncAttributeMaxDynamicSharedMemorySize, NODE_SMEM);
        cudaFuncSetAttribute(edge_kernel, cudaFuncAttributeMaxDynamicSharedMemorySize, EDGE_SMEM);
        int dev = 0, v = 148;
        cudaGetDevice(&dev);
        cudaDeviceGetAttribute(&v, cudaDevAttrMultiProcessorCount, dev);
        sms = (v > 0) ? v : 148;
    }

    zero_kernel<<<256, 256>>>(N);
    int nb = (N + 63) / 64;
    node3_kernel<<<nb, 256, NODE_SMEM>>>(x, W_src, b_src, W_tgt, W_skip, N);
    edge_kernel<<<sms, 256, EDGE_SMEM>>>(ei, W1, b1, W2, b2, Wg, a0, a1, E, N);
    final_kernel<<<(N * 32 + 255) / 256, 256>>>(gamma, beta, out, N);
}